// round 17
// baseline (speedup 1.0000x reference)
#include <cuda_runtime.h>
#include <math.h>
#include <stdint.h>

#define B_   256
#define T_   256
#define INSZ 512
#define HD   1024
#define NBLK 128
#define NTHR 256
#define NCH  24

typedef unsigned long long u64;

// k-major (transposed) operand buffers, built once per launch in init pass
__device__ float g_xT[T_ * INSZ * B_];          // [t][k][b]
__device__ float g_hT[2][4 * HD * B_];          // [pp][s*HD+j][b]
__device__ float g_pT[2][INSZ * B_];            // [pp][o][b]
__device__ float g_WxT[4 * INSZ * 3 * HD];      // [wi][k][J]
__device__ float g_WhT[4 * HD * 3 * HD];
__device__ float g_WoT[4 * (HD + INSZ) * INSZ]; // [wi][k][o]

__device__ unsigned g_count;
__device__ volatile unsigned g_sense;

__device__ __forceinline__ void grid_barrier(unsigned& ls)
{
    __syncthreads();
    if (threadIdx.x == 0) {
        unsigned s = ls ^ 1u;
        __threadfence();
        if (atomicAdd(&g_count, 1u) == NBLK - 1) {
            g_count = 0;
            __threadfence();
            g_sense = s;
        } else {
            while (g_sense != s) { __nanosleep(32); }
        }
        __threadfence();
        ls = s;
    }
    __syncthreads();
}

__device__ __forceinline__ u64 pack2(float lo, float hi)
{ u64 r; asm("mov.b64 %0, {%1, %2};" : "=l"(r) : "f"(lo), "f"(hi)); return r; }
__device__ __forceinline__ void unpack2(u64 v, float& lo, float& hi)
{ asm("mov.b64 {%0, %1}, %2;" : "=f"(lo), "=f"(hi) : "l"(v)); }
__device__ __forceinline__ void ffma2(u64& d, u64 a, u64 b)
{ asm("fma.rn.f32x2 %0, %1, %2, %0;" : "+l"(d) : "l"(a), "l"(b)); }
__device__ __forceinline__ u64 addf2(u64 a, u64 b)
{ u64 r; asm("add.rn.f32x2 %0, %1, %2;" : "=l"(r) : "l"(a), "l"(b)); return r; }

__device__ __forceinline__ uint32_t smem_u32(const void* p)
{ uint32_t a; asm("{ .reg .u64 t; cvta.to.shared.u64 t, %1; cvt.u32.u64 %0, t; }" : "=r"(a) : "l"(p)); return a; }

__device__ __forceinline__ void cp16(uint32_t dst, const float* src)
{ asm volatile("cp.async.cg.shared.global [%0], [%1], 16;" :: "r"(dst), "l"(src)); }

#define CPCOMMIT() asm volatile("cp.async.commit_group;" ::: "memory")
#define CPWAIT1()  asm volatile("cp.async.wait_group 1;" ::: "memory")
#define CPWAIT0()  asm volatile("cp.async.wait_group 0;" ::: "memory")

// stage layout: A tile [64k][64b] floats @0 (16384 B); W tiles @16384
// gate: 3 x [64k][32j] (8192 B each); pred: [64k][16o] (4096 B)
#define STG_B 40960
#define SMEMB (3 * STG_B)

// ---------------- cp.async issue helpers ----------------
__device__ __forceinline__ void issue_gate(uint32_t stg, const float* Ap, const float* Wp, int tid)
{
#pragma unroll
    for (int i = 0; i < 4; i++) {
        int idx = tid + i * 256, row = idx >> 4, seg = idx & 15;
        cp16(stg + row * 256 + seg * 16, Ap + (size_t)row * B_ + seg * 4);
    }
#pragma unroll
    for (int i = 0; i < 6; i++) {
        int idx = tid + i * 256, tile = idx >> 9, rem = idx & 511, row = rem >> 3, seg = rem & 7;
        cp16(stg + 16384 + tile * 8192 + row * 128 + seg * 16,
             Wp + (size_t)row * (3 * HD) + tile * HD + seg * 4);
    }
}

__device__ __forceinline__ void issue_pred(uint32_t stg, const float* Ap, const float* Wp, int tid)
{
#pragma unroll
    for (int i = 0; i < 4; i++) {
        int idx = tid + i * 256, row = idx >> 4, seg = idx & 15;
        cp16(stg + row * 256 + seg * 16, Ap + (size_t)row * B_ + seg * 4);
    }
    { int row = tid >> 2, seg = tid & 3;
      cp16(stg + 16384 + row * 64 + seg * 16, Wp + (size_t)row * INSZ + seg * 4); }
}

__device__ __forceinline__ const float* gate_A(const float* xb_, const float* hb, int c, int b0)
{ return (c < 8) ? xb_ + (size_t)(c * 64) * B_ + b0 : hb + (size_t)((c - 8) * 64) * B_ + b0; }
__device__ __forceinline__ const float* gate_W(const float* wx, const float* wh, int c, int j0)
{ return (c < 8) ? wx + (size_t)(c * 64) * (3 * HD) + j0 : wh + (size_t)((c - 8) * 64) * (3 * HD) + j0; }

// ---------------- compute ----------------
// Gate microtile: 2j x 16b (8 b-pairs), 64 output threads, 4-way k-split.
// Per kk: 4 LDS.128 (A) + 3 LDS.64 (W) + 6 dup-packs + 48 FFMA2 (1.83 B/op).
__device__ __forceinline__ void gate_compute(const char* stg, int gx, int gy, int kh,
    u64 (&au)[2][8], u64 (&ar)[2][8], u64 (&an)[2][8])
{
    const float* As = (const float*)stg;
    const char* W = stg + 16384;
#pragma unroll 4
    for (int kk = 0; kk < 16; kk++) {
        int ka = kh + kk;
        const float* arow = As + ka * 64 + gy * 16;
        ulonglong2 q0 = *(const ulonglong2*)(arow);
        ulonglong2 q1 = *(const ulonglong2*)(arow + 4);
        ulonglong2 q2 = *(const ulonglong2*)(arow + 8);
        ulonglong2 q3 = *(const ulonglong2*)(arow + 12);
        u64 av[8] = {q0.x, q0.y, q1.x, q1.y, q2.x, q2.y, q3.x, q3.y};
        float2 wu = *(const float2*)(W + ka * 128 + gx * 8);
        float2 wr = *(const float2*)(W + 8192 + ka * 128 + gx * 8);
        float2 wn = *(const float2*)(W + 16384 + ka * 128 + gx * 8);
        u64 WU0 = pack2(wu.x, wu.x), WU1 = pack2(wu.y, wu.y);
        u64 WR0 = pack2(wr.x, wr.x), WR1 = pack2(wr.y, wr.y);
        u64 WN0 = pack2(wn.x, wn.x), WN1 = pack2(wn.y, wn.y);
#pragma unroll
        for (int bp = 0; bp < 8; bp++) {
            ffma2(au[0][bp], WU0, av[bp]);
            ffma2(ar[0][bp], WR0, av[bp]);
            ffma2(an[0][bp], WN0, av[bp]);
            ffma2(au[1][bp], WU1, av[bp]);
            ffma2(ar[1][bp], WR1, av[bp]);
            ffma2(an[1][bp], WN1, av[bp]);
        }
    }
}

// Pred microtile: 4o x 8b (4 b-pairs), 32 output threads, 8-way k-split.
__device__ __forceinline__ void pred_compute(const char* stg, int ppx, int ppy, int pkh,
    u64 (&acc)[4][4])
{
    const float* As = (const float*)stg;
    const char* W = stg + 16384;
#pragma unroll
    for (int kk = 0; kk < 8; kk++) {
        int ka = pkh + kk;
        ulonglong2 aA = *(const ulonglong2*)(As + ka * 64 + ppy * 8);
        ulonglong2 aB = *(const ulonglong2*)(As + ka * 64 + ppy * 8 + 4);
        float4 w = *(const float4*)(W + ka * 64 + ppx * 16);
        u64 W0 = pack2(w.x, w.x), W1 = pack2(w.y, w.y);
        u64 W2 = pack2(w.z, w.z), W3 = pack2(w.w, w.w);
        ffma2(acc[0][0], W0, aA.x); ffma2(acc[0][1], W0, aA.y);
        ffma2(acc[0][2], W0, aB.x); ffma2(acc[0][3], W0, aB.y);
        ffma2(acc[1][0], W1, aA.x); ffma2(acc[1][1], W1, aA.y);
        ffma2(acc[1][2], W1, aB.x); ffma2(acc[1][3], W1, aB.y);
        ffma2(acc[2][0], W2, aA.x); ffma2(acc[2][1], W2, aA.y);
        ffma2(acc[2][2], W2, aB.x); ffma2(acc[2][3], W2, aB.y);
        ffma2(acc[3][0], W3, aA.x); ffma2(acc[3][1], W3, aA.y);
        ffma2(acc[3][2], W3, aB.x); ffma2(acc[3][3], W3, aB.y);
    }
}

// ---------------------------------------------------------------------------
__global__ void __launch_bounds__(NTHR) sgru_kernel(
    const float* __restrict__ xb, const float* __restrict__ h0,
    const float* __restrict__ Wx, const float* __restrict__ bx,
    const float* __restrict__ Wh, const float* __restrict__ bh,
    const float* __restrict__ Wo, const float* __restrict__ bo,
    float* __restrict__ out)
{
    extern __shared__ __align__(16) char smx[];
    const uint32_t smb = smem_u32(smx);
    u64* red = (u64*)(smx + 2 * STG_B);   // reductions in stage 2 (free at epilogue)
    const int tid = threadIdx.x, bid = blockIdx.x;
    const int t6 = tid & 63, quarter = tid >> 6, kh = quarter * 16;
    const int gx = t6 & 15, gy = t6 >> 4;       // gate: 16 j-pairs, 4 x 16b
    const int t32 = tid & 31, oct = tid >> 5, pkh = oct * 8;   // pred: 8-way split
    const int ppx = t32 & 3, ppy = t32 >> 2;    // pred: 4 o-quads, 8 x 8b
    unsigned ls = g_sense;

    // ================= init pass: build k-major copies =================
    {
        const long GT = NBLK * NTHR;
        const long g0 = (long)bid * NTHR + tid;
        for (long d = g0; d < (long)T_ * INSZ * B_; d += GT) {
            int b = (int)(d & 255); long rest = d >> 8;
            int k = (int)(rest & 511); int tt = (int)(rest >> 9);
            g_xT[d] = __ldg(xb + ((size_t)b * T_ + tt) * INSZ + k);
        }
        for (long d = g0; d < (long)4 * INSZ * 3 * HD; d += GT) {
            int J = (int)(d % 3072); long rest = d / 3072;
            int k = (int)(rest & 511); int wi = (int)(rest >> 9);
            g_WxT[d] = __ldg(Wx + ((size_t)wi * 3072 + J) * INSZ + k);
        }
        for (long d = g0; d < (long)4 * HD * 3 * HD; d += GT) {
            int J = (int)(d % 3072); long rest = d / 3072;
            int k = (int)(rest & 1023); int wi = (int)(rest >> 10);
            g_WhT[d] = __ldg(Wh + ((size_t)wi * 3072 + J) * HD + k);
        }
        for (long d = g0; d < (long)4 * (HD + INSZ) * INSZ; d += GT) {
            int o = (int)(d & 511); long rest = d >> 9;
            int k = (int)(rest % 1536); int wi = (int)(rest / 1536);
            g_WoT[d] = __ldg(Wo + ((size_t)wi * INSZ + o) * (HD + INSZ) + k);
        }
        for (long d = g0; d < (long)4 * HD * B_; d += GT) {
            int b = (int)(d & 255); long rest = d >> 8;
            int j = (int)(rest & 1023); int s = (int)(rest >> 10);
            g_hT[0][d] = __ldg(h0 + ((size_t)b * 4 + s) * HD + j);
        }
    }
    grid_barrier(ls);

#pragma unroll 1
    for (int t = 0; t < T_; t++) {
        int rd = t & 1, wr = rd ^ 1;
#pragma unroll 1
        for (int s = 0; s < 4; s++) {
            const int wi = (s == 3) ? 2 : s;   // faithful to the source bug
            const float* xbase = (s == 0) ? g_xT + (size_t)t * INSZ * B_
                                          : g_pT[(s - 1) & 1];
            const float* hrdT = g_hT[rd] + (size_t)s * HD * B_;
            float*       hwrT = g_hT[wr] + (size_t)s * HD * B_;
            const float* wxT = g_WxT + (size_t)wi * INSZ * 3 * HD;
            const float* whT = g_WhT + (size_t)wi * HD * 3 * HD;
            const float* woT = g_WoT + (size_t)wi * (HD + INSZ) * INSZ;

            const int j0 = (bid & 31) * 32;
            const int o0 = (bid & 31) * 16;
            const int b0 = (bid >> 5) * 64;

            // ================= GATE =================
            {
                issue_gate(smb, gate_A(xbase, hrdT, 0, b0), gate_W(wxT, whT, 0, j0), tid); CPCOMMIT();
                issue_gate(smb + STG_B, gate_A(xbase, hrdT, 1, b0), gate_W(wxT, whT, 1, j0), tid); CPCOMMIT();

                u64 au[2][8], ar[2][8], axn[2][8], ahn[2][8];
                const float* bx3 = bx + wi * 3 * HD;
                const float* bh3 = bh + wi * 3 * HD;
                const int jg = j0 + gx * 2;
                if (quarter == 0) {
#pragma unroll
                    for (int j = 0; j < 2; j++) {
                        float bu = bx3[jg + j] + bh3[jg + j];
                        float br = bx3[HD + jg + j] + bh3[HD + jg + j];
                        float bxn = bx3[2 * HD + jg + j];
                        float bhn = bh3[2 * HD + jg + j];
#pragma unroll
                        for (int bp = 0; bp < 8; bp++) {
                            au[j][bp] = pack2(bu, bu); ar[j][bp] = pack2(br, br);
                            axn[j][bp] = pack2(bxn, bxn); ahn[j][bp] = pack2(bhn, bhn);
                        }
                    }
                } else {
#pragma unroll
                    for (int j = 0; j < 2; j++)
#pragma unroll
                        for (int bp = 0; bp < 8; bp++) {
                            au[j][bp] = 0; ar[j][bp] = 0; axn[j][bp] = 0; ahn[j][bp] = 0;
                        }
                }
#pragma unroll 1
                for (int c = 0; c < NCH; c++) {
                    if (c < NCH - 1) CPWAIT1(); else CPWAIT0();
                    __syncthreads();
                    if (c + 2 < NCH) {
                        issue_gate(smb + ((c + 2) % 3) * STG_B,
                                   gate_A(xbase, hrdT, c + 2, b0),
                                   gate_W(wxT, whT, c + 2, j0), tid);
                        CPCOMMIT();
                    }
                    if (c < 8)
                        gate_compute(smx + (c % 3) * STG_B, gx, gy, kh, au, ar, axn);
                    else
                        gate_compute(smx + (c % 3) * STG_B, gx, gy, kh, au, ar, ahn);
                }
                // staged cross-quarter reduction (stage 2 free now)
                __syncthreads();
#pragma unroll 1
                for (int q = 1; q < 4; q++) {
                    if (quarter == q) {
                        u64* rp = red + (size_t)t6 * 65;
#pragma unroll
                        for (int j = 0; j < 2; j++)
#pragma unroll
                            for (int bp = 0; bp < 8; bp++) {
                                rp[j * 8 + bp] = au[j][bp];
                                rp[16 + j * 8 + bp] = ar[j][bp];
                                rp[32 + j * 8 + bp] = axn[j][bp];
                                rp[48 + j * 8 + bp] = ahn[j][bp];
                            }
                    }
                    __syncthreads();
                    if (quarter == 0) {
                        u64* rp = red + (size_t)t6 * 65;
#pragma unroll
                        for (int j = 0; j < 2; j++)
#pragma unroll
                            for (int bp = 0; bp < 8; bp++) {
                                au[j][bp] = addf2(au[j][bp], rp[j * 8 + bp]);
                                ar[j][bp] = addf2(ar[j][bp], rp[16 + j * 8 + bp]);
                                axn[j][bp] = addf2(axn[j][bp], rp[32 + j * 8 + bp]);
                                ahn[j][bp] = addf2(ahn[j][bp], rp[48 + j * 8 + bp]);
                            }
                    }
                    __syncthreads();
                }
                if (quarter == 0) {
                    // epilogue: 2j x 16b per thread (float2 over b-pairs)
#pragma unroll
                    for (int j = 0; j < 2; j++) {
                        size_t rowo = (size_t)(jg + j) * B_;
#pragma unroll
                        for (int bp = 0; bp < 8; bp++) {
                            int b = b0 + gy * 16 + bp * 2;
                            float u0, u1, r0, r1, x0, x1, hn0, hn1;
                            unpack2(au[j][bp], u0, u1);
                            unpack2(ar[j][bp], r0, r1);
                            unpack2(axn[j][bp], x0, x1);
                            unpack2(ahn[j][bp], hn0, hn1);
                            float2 ho = __ldcg((const float2*)(hrdT + rowo + b));
                            float ua = 1.0f / (1.0f + expf(-u0));
                            float ub = 1.0f / (1.0f + expf(-u1));
                            float ra = 1.0f / (1.0f + expf(-r0));
                            float rb = 1.0f / (1.0f + expf(-r1));
                            float na = tanhf(x0 + ra * hn0);
                            float nb = tanhf(x1 + rb * hn1);
                            float2 hv = make_float2(ua * ho.x + (1.0f - ua) * na,
                                                    ub * ho.y + (1.0f - ub) * nb);
                            *(float2*)(hwrT + rowo + b) = hv;
                        }
                    }
                }
            }
            // pred prologue (x-chunks + immutable Wo): safe before the barrier
            issue_pred(smb, gate_A(xbase, g_hT[wr] + (size_t)s * HD * B_, 0, b0),
                       woT + 0 * INSZ + o0, tid); CPCOMMIT();
            issue_pred(smb + STG_B, gate_A(xbase, g_hT[wr] + (size_t)s * HD * B_, 1, b0),
                       woT + (size_t)64 * INSZ + o0, tid); CPCOMMIT();
            grid_barrier(ls);

            // ================= PRED =================
            {
                const float* hnT = g_hT[wr] + (size_t)s * HD * B_;
                const float* bop = bo + wi * INSZ;
                u64 acc[4][4];
                if (oct == 0) {
#pragma unroll
                    for (int j = 0; j < 4; j++) {
                        float bv = bop[o0 + ppx * 4 + j];
#pragma unroll
                        for (int bp = 0; bp < 4; bp++) acc[j][bp] = pack2(bv, bv);
                    }
                } else {
#pragma unroll
                    for (int j = 0; j < 4; j++)
#pragma unroll
                        for (int bp = 0; bp < 4; bp++) acc[j][bp] = 0;
                }
#pragma unroll 1
                for (int c = 0; c < NCH; c++) {
                    if (c < NCH - 1) CPWAIT1(); else CPWAIT0();
                    __syncthreads();
                    if (c + 2 < NCH) {
                        issue_pred(smb + ((c + 2) % 3) * STG_B,
                                   gate_A(xbase, hnT, c + 2, b0),
                                   woT + (size_t)((c + 2) * 64) * INSZ + o0, tid);
                        CPCOMMIT();
                    }
                    pred_compute(smx + (c % 3) * STG_B, ppx, ppy, pkh, acc);
                }
                // cross-octave reduction (stage 2 free)
                __syncthreads();
                if (oct) {
                    u64* rp = red + ((size_t)(oct - 1) * 32 + t32) * 17;
#pragma unroll
                    for (int j = 0; j < 4; j++)
#pragma unroll
                        for (int bp = 0; bp < 4; bp++) rp[j * 4 + bp] = acc[j][bp];
                }
                __syncthreads();
                if (oct == 0) {
#pragma unroll
                    for (int q = 0; q < 7; q++) {
                        u64* rp = red + ((size_t)q * 32 + t32) * 17;
#pragma unroll
                        for (int j = 0; j < 4; j++)
#pragma unroll
                            for (int bp = 0; bp < 4; bp++)
                                acc[j][bp] = addf2(acc[j][bp], rp[j * 4 + bp]);
                    }
                    // epilogue: 4o x 8b per thread
#pragma unroll
                    for (int j = 0; j < 4; j++) {
                        int o = o0 + ppx * 4 + j;
#pragma unroll
                        for (int bp = 0; bp < 4; bp++) {
                            int b = b0 + ppy * 8 + bp * 2;
                            float v0, v1;
                            unpack2(acc[j][bp], v0, v1);
                            if (s == 3) {
                                out[((size_t)b * T_ + t) * INSZ + o] = v0;
                                out[((size_t)(b + 1) * T_ + t) * INSZ + o] = v1;
                            } else {
                                *(float2*)(g_pT[s & 1] + (size_t)o * B_ + b) = make_float2(v0, v1);
                            }
                        }
                    }
                }
            }
            grid_barrier(ls);
        }
    }

    // ---- final h copy-out (hT[0] -> out tail, standard layout) ----
    {
        const long GT = NBLK * NTHR;
        for (long d = (long)bid * NTHR + tid; d < (long)B_ * 4 * HD; d += GT) {
            int j = (int)(d & 1023); long rest = d >> 10;
            int s = (int)(rest & 3); int b = (int)(rest >> 2);
            out[(size_t)B_ * T_ * INSZ + d] = __ldcg(&g_hT[0][((size_t)s * HD + j) * B_ + b]);
        }
    }
    // ---- log_softmax over each 512-wide pred row ----
    {
        int w = tid >> 5, ln = tid & 31;
        int gw = bid * 8 + w;
#pragma unroll 1
        for (int r = gw; r < B_ * T_; r += NBLK * 8) {
            float* p = out + (size_t)r * INSZ;
            float v[16], m = -1e30f;
#pragma unroll
            for (int i = 0; i < 16; i++) { v[i] = __ldcg(p + ln + i * 32); m = fmaxf(m, v[i]); }
#pragma unroll
            for (int o = 16; o > 0; o >>= 1) m = fmaxf(m, __shfl_xor_sync(~0u, m, o));
            float sv = 0.0f;
#pragma unroll
            for (int i = 0; i < 16; i++) sv += expf(v[i] - m);
#pragma unroll
            for (int o = 16; o > 0; o >>= 1) sv += __shfl_xor_sync(~0u, sv, o);
            float lv = m + logf(sv);
#pragma unroll
            for (int i = 0; i < 16; i++) p[ln + i * 32] = v[i] - lv;
        }
    }
}

// ---------------------------------------------------------------------------
extern "C" void kernel_launch(void* const* d_in, const int* in_sizes, int n_in,
                              void* d_out, int out_size)
{
    cudaFuncSetAttribute(sgru_kernel, cudaFuncAttributeMaxDynamicSharedMemorySize, SMEMB);
    sgru_kernel<<<NBLK, NTHR, SMEMB>>>(
        (const float*)d_in[0], (const float*)d_in[1], (const float*)d_in[2],
        (const float*)d_in[3], (const float*)d_in[4], (const float*)d_in[5],
        (const float*)d_in[6], (const float*)d_in[7], (float*)d_out);
}